// round 16
// baseline (speedup 1.0000x reference)
#include <cuda_runtime.h>
#include <cuda_bf16.h>
#include <math.h>
#include <stdint.h>

// Problem constants
#define B_      64
#define N1_     512
#define N2_     512
#define NPER    1024
#define NTOT    65536
#define KSEL    256
#define NPOOL   16384
#define E_ALL   1048576
#define E_C     524288

// ---------------- scratch ----------------
__device__ float g_h0[(size_t)NTOT * 128];
__device__ float g_h1[(size_t)NTOT * 128];
__device__ float g_h2[(size_t)NTOT * 128];
__device__ float g_xw[(size_t)NTOT * 128];
__device__ float g_dis[NTOT];

// CSR for the big graph
__device__ int g_degI[NTOT];
__device__ int g_rowstart[NTOT];
__device__ int g_cursor[NTOT];
__device__ int g_ecol[E_ALL];
__device__ int g_ctr[2];

__device__ float g_mean[128 * 384];
__device__ float g_catt[128 * 384];
__device__ float g_gp[128 * 384];
__device__ float g_pv[64 * 768];
__device__ float g_pvnorm[128];

__device__ float g_score[2][B_ * N1_];
__device__ int   g_map[2][B_ * N1_];
__device__ int   g_perm[2][B_ * KSEL];

// pooled CSR (combined over both clusters)
__device__ int   g_degPI[2 * NPOOL];
__device__ int   g_rowstartP[2 * NPOOL];
__device__ int   g_cursorP[2 * NPOOL];
__device__ int   g_ecolP[2 * E_C];
__device__ float g_disP[2 * NPOOL];

__device__ float g_xwP[(size_t)2 * NPOOL * 128];
__device__ float g_hP[2][(size_t)NPOOL * 128];

__device__ float g_meanF[2][B_ * 128];
__device__ float g_cF[2][B_ * 128];
__device__ float g_gfin[2][B_ * 128];

__device__ __forceinline__ float xcat_at(int node, int f) {
    const float* H = (f < 128) ? g_h0 : ((f < 256) ? g_h1 : g_h2);
    return H[(size_t)node * 128 + (f & 127)];
}
__device__ __forceinline__ float sigmoidf_(float x) { return 1.f / (1.f + expf(-x)); }

// ---------------- zero everything that accumulates ----------------
__global__ void zero_all_kernel() {
    const int NM = 128 * 384;
    int stride = gridDim.x * blockDim.x;
    for (int i = blockIdx.x * blockDim.x + threadIdx.x;
         i < NTOT + 2 * NPOOL + 2 + 2 * NM + 2 * 2 * B_ * 128; i += stride) {
        int j = i;
        if (j < NTOT) { g_degI[j] = 0; continue; }
        j -= NTOT;
        if (j < 2 * NPOOL) { g_degPI[j] = 0; continue; }
        j -= 2 * NPOOL;
        if (j < 2) { g_ctr[j] = 0; continue; }
        j -= 2;
        if (j < NM) { g_mean[j] = 0.f; continue; }
        j -= NM;
        if (j < NM) { g_gp[j] = 0.f; continue; }
        j -= NM;
        if (j < 2 * B_ * 128) { ((float*)g_meanF)[j] = 0.f; continue; }
        j -= 2 * B_ * 128;
        ((float*)g_gfin)[j] = 0.f;
    }
}

__global__ void degi_kernel(const int* __restrict__ dst, int* __restrict__ deg, int E) {
    int e = blockIdx.x * blockDim.x + threadIdx.x;
    if (e < E) atomicAdd(&deg[dst[e]], 1);
}

// combined pooled degree count over both clusters
__global__ void degPI2_kernel(const int* __restrict__ src0, const int* __restrict__ dst0,
                              const int* __restrict__ src1, const int* __restrict__ dst1) {
    int e = blockIdx.x * blockDim.x + threadIdx.x;
    if (e < E_C) {
        int r = g_map[0][src0[e]], c = g_map[0][dst0[e]];
        if (r >= 0 && c >= 0) atomicAdd(&g_degPI[c], 1);
    } else {
        e -= E_C;
        int r = g_map[1][src1[e]], c = g_map[1][dst1[e]];
        if (r >= 0 && c >= 0) atomicAdd(&g_degPI[NPOOL + c], 1);
    }
}

// rowstart assignment without scans: order-free atomic range grab.
__global__ void assign_kernel(const int* __restrict__ deg, int* __restrict__ rowstart,
                              int* __restrict__ cursor, float* __restrict__ dis,
                              int n, int* __restrict__ ctr) {
    int i = blockIdx.x * blockDim.x + threadIdx.x;
    if (i >= n) return;
    int d = deg[i];
    int rs = atomicAdd(ctr, d);
    rowstart[i] = rs;
    cursor[i] = rs;
    dis[i] = rsqrtf((float)d + 1.f);
}

// ---------------- CSR edge placement (cursor pre-seeded with rowstart) ----------------
__global__ void place_kernel(const int* __restrict__ src, const int* __restrict__ dst,
                             int* __restrict__ cursor, int* __restrict__ ecol, int E) {
    int e = blockIdx.x * blockDim.x + threadIdx.x;
    if (e >= E) return;
    int pos = atomicAdd(&cursor[dst[e]], 1);
    ecol[pos] = src[e];
}
// combined pooled placement over both clusters
__global__ void placeP2_kernel(const int* __restrict__ src0, const int* __restrict__ dst0,
                               const int* __restrict__ src1, const int* __restrict__ dst1) {
    int e = blockIdx.x * blockDim.x + threadIdx.x;
    int cl = 0, off = 0;
    const int* S = src0;
    const int* D = dst0;
    if (e >= E_C) { e -= E_C; S = src1; D = dst1; cl = 1; off = NPOOL; }
    int r = g_map[cl][S[e]], c = g_map[cl][D[e]];
    if (r < 0 || c < 0) return;
    int pos = atomicAdd(&g_cursorP[c + off], 1);
    g_ecolP[pos] = r + off;
}

// ============ 3xBF16 tensor-core GEMM (m16n8k16, interleaved H/L, double-buffered) ============
// x = hi + lo (both bf16); acc += aL*bH + aH*bL + aH*bH  (~2^-16 effective input precision)
__device__ __forceinline__ void mma_bf16(float* c, const uint32_t* a, uint32_t b0, uint32_t b1) {
    asm volatile("mma.sync.aligned.m16n8k16.row.col.f32.bf16.bf16.f32 "
                 "{%0,%1,%2,%3}, {%4,%5,%6,%7}, {%8,%9}, {%0,%1,%2,%3};"
                 : "+f"(c[0]), "+f"(c[1]), "+f"(c[2]), "+f"(c[3])
                 : "r"(a[0]), "r"(a[1]), "r"(a[2]), "r"(a[3]), "r"(b0), "r"(b1));
}

// pack a k-pair (x = k, y = k+1) into hi-plane and lo-plane bf16x2 words
__device__ __forceinline__ void split2_bf16(float x, float y, uint32_t& hi, uint32_t& lo) {
    __nv_bfloat16 xh = __float2bfloat16(x);
    __nv_bfloat16 yh = __float2bfloat16(y);
    __nv_bfloat16 xl = __float2bfloat16(x - __bfloat162float(xh));
    __nv_bfloat16 yl = __float2bfloat16(y - __bfloat162float(yh));
    hi = ((uint32_t)__bfloat16_as_ushort(yh) << 16) | (uint32_t)__bfloat16_as_ushort(xh);
    lo = ((uint32_t)__bfloat16_as_ushort(yl) << 16) | (uint32_t)__bfloat16_as_ushort(xl);
}

// smem layout (u32 words), H/L interleaved per element:
//   A: 128 rows x STA(=40: 16 kpairs x {H,L} = 32 data + 8 pad); 40 % 32 == 8 ->
//      fragment LDS.64 banks 8r + 2k distinct per 16-lane phase.
//   B: 16 kpair-rows x STB(=264: 128 cols x {H,L} = 256 data + 8 pad); 264 % 32 == 8 ->
//      fragment LDS.64 banks 8k + 2n distinct.
#define STA 40
#define STB 264
#define A_PLANE (128 * STA)            // 5120 words
#define B_PLANE (16 * STB)             // 4224 words
#define BUF_WORDS (A_PLANE + B_PLANE)  // 9344 words = 37376 B
#define GEMM_SMEM (2 * BUF_WORDS * 4)  // 74752 B (double buffered)

__device__ __forceinline__ void ldgA_dense(const float* __restrict__ A, int K, int R0, int k0,
                                           int tid, float4* ra) {
#pragma unroll
    for (int i = 0; i < 4; i++) {
        int q = tid + i * 256;
        int r = q >> 3, c4 = (q & 7) << 2;
        ra[i] = *(const float4*)(A + (size_t)(R0 + r) * K + k0 + c4);
    }
}
__device__ __forceinline__ void ldgB(const float* __restrict__ W, int k0, int tid,
                                     float2* rb0, float2* rb1) {
#pragma unroll
    for (int i = 0; i < 4; i++) {
        int Q = tid + i * 256;
        int kp = Q >> 6;
        int c2 = (Q & 63) << 1;
        rb0[i] = *(const float2*)(W + (size_t)(k0 + 2 * kp) * 128 + c2);
        rb1[i] = *(const float2*)(W + (size_t)(k0 + 2 * kp + 1) * 128 + c2);
    }
}

__device__ __forceinline__ void sts_buf(float* buf, int tid, const float4* ra,
                                        const float2* rb0, const float2* rb1) {
    uint32_t* As = (uint32_t*)buf;            // [row][2*kp + {0=H,1=L}]
    uint32_t* Bs = As + A_PLANE;              // [kp][2*n + {0=H,1=L}]
#pragma unroll
    for (int i = 0; i < 4; i++) {
        int q = tid + i * 256;
        int r = q >> 3, kq = q & 7;           // kpairs 2*kq, 2*kq+1
        uint32_t h0, l0, h1, l1;
        split2_bf16(ra[i].x, ra[i].y, h0, l0);
        split2_bf16(ra[i].z, ra[i].w, h1, l1);
        uint4 v = make_uint4(h0, l0, h1, l1);
        *(uint4*)(As + r * STA + 4 * kq) = v;  // words 2*(2kq)..2*(2kq)+3
    }
#pragma unroll
    for (int i = 0; i < 4; i++) {
        int Q = tid + i * 256;
        int kp = Q >> 6, c2 = (Q & 63) << 1;
        uint32_t hA, lA, hB, lB;
        split2_bf16(rb0[i].x, rb1[i].x, hA, lA);   // col c2:   (k, k+1)
        split2_bf16(rb0[i].y, rb1[i].y, hB, lB);   // col c2+1: (k, k+1)
        uint4 v = make_uint4(hA, lA, hB, lB);
        *(uint4*)(Bs + kp * STB + 2 * c2) = v;
    }
}

__device__ __forceinline__ void compute_buf(const float* buf, int lane, int mw, int nw,
                                            float c[2][8][4]) {
    const uint32_t* As = (const uint32_t*)buf;
    const uint32_t* Bs = As + A_PLANE;
#pragma unroll
    for (int step = 0; step < 2; step++) {
        int kpb = step * 8 + (lane & 3);
        uint32_t aH[2][4], aL[2][4];
#pragma unroll
        for (int mi = 0; mi < 2; mi++) {
            int r = mw * 32 + mi * 16 + (lane >> 2);
            uint2 v0 = *(const uint2*)(As + r * STA + 2 * kpb);             // (H,L) kpb
            uint2 v1 = *(const uint2*)(As + (r + 8) * STA + 2 * kpb);
            uint2 v2 = *(const uint2*)(As + r * STA + 2 * kpb + 8);         // kpb+4
            uint2 v3 = *(const uint2*)(As + (r + 8) * STA + 2 * kpb + 8);
            aH[mi][0] = v0.x; aL[mi][0] = v0.y;
            aH[mi][1] = v1.x; aL[mi][1] = v1.y;
            aH[mi][2] = v2.x; aL[mi][2] = v2.y;
            aH[mi][3] = v3.x; aL[mi][3] = v3.y;
        }
#pragma unroll
        for (int ni = 0; ni < 8; ni++) {
            int n = nw * 64 + ni * 8 + (lane >> 2);
            uint2 b0 = *(const uint2*)(Bs + kpb * STB + 2 * n);             // (H,L) kpb
            uint2 b1 = *(const uint2*)(Bs + (kpb + 4) * STB + 2 * n);       // kpb+4
            uint32_t bH0 = b0.x, bL0 = b0.y;
            uint32_t bH1 = b1.x, bL1 = b1.y;
            mma_bf16(c[0][ni], aL[0], bH0, bH1);
            mma_bf16(c[1][ni], aL[1], bH0, bH1);
            mma_bf16(c[0][ni], aH[0], bL0, bL1);
            mma_bf16(c[1][ni], aH[1], bL0, bL1);
            mma_bf16(c[0][ni], aH[0], bH0, bH1);
            mma_bf16(c[1][ni], aH[1], bH0, bH1);
        }
    }
}

__device__ __forceinline__ void gemm_epilogue(int lane, int mw, int nw, int R0,
                                              float c[2][8][4], float* __restrict__ C)
{
#pragma unroll
    for (int mi = 0; mi < 2; mi++) {
#pragma unroll
        for (int ni = 0; ni < 8; ni++) {
            int row = R0 + mw * 32 + mi * 16 + (lane >> 2);
            int col = nw * 64 + ni * 8 + 2 * (lane & 3);
            *(float2*)(C + (size_t)row * 128 + col) = make_float2(c[mi][ni][0], c[mi][ni][1]);
            *(float2*)(C + (size_t)(row + 8) * 128 + col) = make_float2(c[mi][ni][2], c[mi][ni][3]);
        }
    }
}

__global__ void __launch_bounds__(256, 2) gemm_bf16(
    const float* __restrict__ A, const float* __restrict__ W,
    float* __restrict__ C, int K)
{
    extern __shared__ float sm[];
    int tid = threadIdx.x, lane = tid & 31, w = tid >> 5;
    int mw = w >> 1, nw = w & 1;
    int R0 = blockIdx.x * 128;

    float c[2][8][4];
#pragma unroll
    for (int mi = 0; mi < 2; mi++)
#pragma unroll
        for (int ni = 0; ni < 8; ni++)
#pragma unroll
            for (int k = 0; k < 4; k++) c[mi][ni][k] = 0.f;

    float4 ra[4];
    float2 rb0[4], rb1[4];
    ldgA_dense(A, K, R0, 0, tid, ra);
    ldgB(W, 0, tid, rb0, rb1);
    sts_buf(sm, tid, ra, rb0, rb1);

    int nch = K >> 5;
    for (int ch = 0; ch < nch; ch++) {
        __syncthreads();
        if (ch + 1 < nch) {
            ldgA_dense(A, K, R0, (ch + 1) << 5, tid, ra);
            ldgB(W, (ch + 1) << 5, tid, rb0, rb1);
        }
        compute_buf(sm + (ch & 1) * BUF_WORDS, lane, mw, nw, c);
        if (ch + 1 < nch)
            sts_buf(sm + ((ch + 1) & 1) * BUF_WORDS, tid, ra, rb0, rb1);
    }
    gemm_epilogue(lane, mw, nw, R0, c, C);
}

// ---- pooled GEMM with fused gather: A[row][k] = xcat(node(row),k) * gate(row); K=384 ----
__global__ void __launch_bounds__(256, 2) gemm_pool(
    const float* __restrict__ W, float* __restrict__ C)
{
    extern __shared__ float sm[];
    int tid = threadIdx.x, lane = tid & 31, w = tid >> 5;
    int mw = w >> 1, nw = w & 1;
    int R0 = blockIdx.x * 128;

    const float* Hs[3] = { g_h0, g_h1, g_h2 };
    int nodeR[4];
    float gateR[4];
#pragma unroll
    for (int i = 0; i < 4; i++) {
        int q = tid + i * 256;
        int r = q >> 3;
        int row = R0 + r;
        int cl = row >> 14;
        int rr = row & (NPOOL - 1);
        int g = rr >> 8;
        int j = g_perm[cl][rr];
        nodeR[i] = g * NPER + cl * N1_ + j;
        gateR[i] = sigmoidf_(g_score[cl][g * 512 + j]);
    }

    float c[2][8][4];
#pragma unroll
    for (int mi = 0; mi < 2; mi++)
#pragma unroll
        for (int ni = 0; ni < 8; ni++)
#pragma unroll
            for (int k = 0; k < 4; k++) c[mi][ni][k] = 0.f;

    float4 ra[4];
    float2 rb0[4], rb1[4];
    auto ldgA_pool = [&](int k0) {
        const float* H = Hs[k0 >> 7];
        int kloc = k0 & 127;
#pragma unroll
        for (int i = 0; i < 4; i++) {
            int q = tid + i * 256;
            int c4 = (q & 7) << 2;
            float4 v = *(const float4*)(H + (size_t)nodeR[i] * 128 + kloc + c4);
            float gt = gateR[i];
            v.x *= gt; v.y *= gt; v.z *= gt; v.w *= gt;
            ra[i] = v;
        }
    };

    ldgA_pool(0);
    ldgB(W, 0, tid, rb0, rb1);
    sts_buf(sm, tid, ra, rb0, rb1);

    const int nch = 384 >> 5;   // 12
    for (int ch = 0; ch < nch; ch++) {
        __syncthreads();
        if (ch + 1 < nch) {
            ldgA_pool((ch + 1) << 5);
            ldgB(W, (ch + 1) << 5, tid, rb0, rb1);
        }
        compute_buf(sm + (ch & 1) * BUF_WORDS, lane, mw, nw, c);
        if (ch + 1 < nch)
            sts_buf(sm + ((ch + 1) & 1) * BUF_WORDS, tid, ra, rb0, rb1);
    }
    gemm_epilogue(lane, mw, nw, R0, c, C);
}

// ---------------- CSR gather-aggregate + self loop + bias + relu (4-way unrolled) ----------------
__global__ void __launch_bounds__(256) agg_kernel(
    const float* __restrict__ xw,
    const int* __restrict__ rowstart, const int* __restrict__ degI,
    const int* __restrict__ ecol, const float* __restrict__ dis,
    const float* __restrict__ bias, float* __restrict__ out, int n)
{
    int w = (blockIdx.x * blockDim.x + threadIdx.x) >> 5;
    if (w >= n) return;
    int lane = threadIdx.x & 31;
    int rs = rowstart[w];
    int re = rs + degI[w];
    float4 a0 = make_float4(0.f, 0.f, 0.f, 0.f);
    float4 a1 = make_float4(0.f, 0.f, 0.f, 0.f);
    float4 a2 = make_float4(0.f, 0.f, 0.f, 0.f);
    float4 a3 = make_float4(0.f, 0.f, 0.f, 0.f);
    int i = rs;
    for (; i + 4 <= re; i += 4) {
        int s0 = ecol[i], s1 = ecol[i + 1], s2 = ecol[i + 2], s3 = ecol[i + 3];
        float w0 = dis[s0], w1 = dis[s1], w2 = dis[s2], w3 = dis[s3];
        float4 v0 = *(const float4*)(xw + (size_t)s0 * 128 + lane * 4);
        float4 v1 = *(const float4*)(xw + (size_t)s1 * 128 + lane * 4);
        float4 v2 = *(const float4*)(xw + (size_t)s2 * 128 + lane * 4);
        float4 v3 = *(const float4*)(xw + (size_t)s3 * 128 + lane * 4);
        a0.x = fmaf(v0.x, w0, a0.x); a0.y = fmaf(v0.y, w0, a0.y);
        a0.z = fmaf(v0.z, w0, a0.z); a0.w = fmaf(v0.w, w0, a0.w);
        a1.x = fmaf(v1.x, w1, a1.x); a1.y = fmaf(v1.y, w1, a1.y);
        a1.z = fmaf(v1.z, w1, a1.z); a1.w = fmaf(v1.w, w1, a1.w);
        a2.x = fmaf(v2.x, w2, a2.x); a2.y = fmaf(v2.y, w2, a2.y);
        a2.z = fmaf(v2.z, w2, a2.z); a2.w = fmaf(v2.w, w2, a2.w);
        a3.x = fmaf(v3.x, w3, a3.x); a3.y = fmaf(v3.y, w3, a3.y);
        a3.z = fmaf(v3.z, w3, a3.z); a3.w = fmaf(v3.w, w3, a3.w);
    }
    for (; i < re; i++) {
        int s0 = ecol[i];
        float w0 = dis[s0];
        float4 v0 = *(const float4*)(xw + (size_t)s0 * 128 + lane * 4);
        a0.x = fmaf(v0.x, w0, a0.x); a0.y = fmaf(v0.y, w0, a0.y);
        a0.z = fmaf(v0.z, w0, a0.z); a0.w = fmaf(v0.w, w0, a0.w);
    }
    a0.x += a1.x + a2.x + a3.x;
    a0.y += a1.y + a2.y + a3.y;
    a0.z += a1.z + a2.z + a3.z;
    a0.w += a1.w + a2.w + a3.w;
    float dd = dis[w];
    float sw = dd * dd;
    float4 self = *(const float4*)(xw + (size_t)w * 128 + lane * 4);
    float4 r;
    r.x = fmaxf(fmaf(a0.x, dd, fmaf(self.x, sw, bias[lane * 4 + 0])), 0.f);
    r.y = fmaxf(fmaf(a0.y, dd, fmaf(self.y, sw, bias[lane * 4 + 1])), 0.f);
    r.z = fmaxf(fmaf(a0.z, dd, fmaf(self.z, sw, bias[lane * 4 + 2])), 0.f);
    r.w = fmaxf(fmaf(a0.w, dd, fmaf(self.w, sw, bias[lane * 4 + 3])), 0.f);
    *(float4*)(out + (size_t)w * 128 + lane * 4) = r;
}

// ---------------- attention pool (big, 384 feats) ----------------
__global__ void mean384_kernel() {
    int s = blockIdx.x >> 2, ch = blockIdx.x & 3;
    int f = threadIdx.x;
    int g = s & 63, cl = s >> 6;
    int base = g * NPER + cl * N1_ + ch * 128;
    float acc = 0.f;
#pragma unroll 4
    for (int j = 0; j < 128; j++) acc += xcat_at(base + j, f);
    atomicAdd(&g_mean[s * 384 + f], acc);
}

__global__ void catt_kernel(const float* __restrict__ Wg) {
    __shared__ float m[384];
    int s = blockIdx.x, f = threadIdx.x;
    m[f] = g_mean[s * 384 + f] * (1.f / 512.f);
    __syncthreads();
    float acc = 0.f;
    for (int k = 0; k < 384; k++) acc = fmaf(m[k], Wg[k * 384 + f], acc);
    g_catt[s * 384 + f] = tanhf(acc);
}

// fused alpha + gp: one xcat pass.
__global__ void __launch_bounds__(256) alphagp_kernel() {
    int blk = blockIdx.x;
    int s = blk >> 3, ch = blk & 7;
    int g = s & 63, cl = s >> 6;
    int base = g * NPER + cl * N1_ + ch * 64;
    int wid = threadIdx.x >> 5, lane = threadIdx.x & 31;
    __shared__ float csh[384];
    __shared__ float gpsh[384];
    for (int t = threadIdx.x; t < 384; t += 256) { csh[t] = g_catt[s * 384 + t]; gpsh[t] = 0.f; }
    __syncthreads();
    float acc[12];
#pragma unroll
    for (int q = 0; q < 12; q++) acc[q] = 0.f;
    for (int j = 0; j < 8; j++) {
        int node = base + wid * 8 + j;
        float xv[12];
        float dot = 0.f;
#pragma unroll
        for (int q = 0; q < 12; q++) {
            int f = q * 32 + lane;
            xv[q] = xcat_at(node, f);
            dot = fmaf(xv[q], csh[f], dot);
        }
#pragma unroll
        for (int o = 16; o; o >>= 1) dot += __shfl_xor_sync(0xffffffffu, dot, o);
        float alpha = sigmoidf_(dot);
#pragma unroll
        for (int q = 0; q < 12; q++) acc[q] = fmaf(xv[q], alpha, acc[q]);
    }
#pragma unroll
    for (int q = 0; q < 12; q++) atomicAdd(&gpsh[q * 32 + lane], acc[q]);
    __syncthreads();
    for (int t = threadIdx.x; t < 384; t += 256) atomicAdd(&g_gp[s * 384 + t], gpsh[t]);
}

__global__ void pv_kernel(const float* __restrict__ Wal, const float* __restrict__ bal) {
    __shared__ float in[768];
    int g = blockIdx.x, t = threadIdx.x;
    in[t] = (t < 384) ? g_gp[g * 384 + t] : g_gp[(64 + g) * 384 + (t - 384)];
    __syncthreads();
    float acc = bal[t];
    for (int k = 0; k < 768; k++) acc = fmaf(in[k], Wal[k * 768 + t], acc);
    g_pv[g * 768 + t] = acc;
}

__global__ void pvnorm_kernel() {
    int b = blockIdx.x;
    int cl = b >> 6, g = b & 63;
    int t = threadIdx.x;
    float acc = 0.f;
    for (int k = t; k < 384; k += 128) {
        float v = g_pv[g * 768 + cl * 384 + k];
        acc += v * v;
    }
    __shared__ float red[128];
    red[t] = acc;
    __syncthreads();
    for (int o = 64; o; o >>= 1) {
        if (t < o) red[t] += red[t + o];
        __syncthreads();
    }
    if (!t) g_pvnorm[b] = sqrtf(red[0]);
}

// ---------------- CAG pool ----------------
__global__ void score_kernel() {
    int w = (blockIdx.x * blockDim.x + threadIdx.x) >> 5;
    if (w >= NTOT) return;
    int lane = threadIdx.x & 31;
    int cl = w >> 15;
    int rem = w & 32767;
    int g = rem >> 9, j = rem & 511;
    int node = g * NPER + cl * N1_ + j;
    const float* q = g_pv + g * 768 + cl * 384;
    float acc = 0.f;
    for (int t = lane; t < 384; t += 32) acc += xcat_at(node, t) * q[t];
#pragma unroll
    for (int o = 16; o; o >>= 1) acc += __shfl_xor_sync(0xffffffffu, acc, o);
    if (!lane) g_score[cl][g * 512 + j] = acc / g_pvnorm[cl * 64 + g];
}

__global__ void topk_kernel() {
    int b = blockIdx.x;
    int cl = b >> 6, g = b & 63;
    int j = threadIdx.x;
    __shared__ float s[512];
    s[j] = g_score[cl][g * 512 + j];
    __syncthreads();
    float mys = s[j];
    int rank = 0;
    for (int i = 0; i < 512; i++) {
        float o = s[i];
        rank += (o > mys) || (o == mys && i < j);
    }
    g_map[cl][g * 512 + j] = (rank < KSEL) ? (g * KSEL + rank) : -1;
    if (rank < KSEL) g_perm[cl][g * KSEL + rank] = j;
}

// ---------------- final attention pool ----------------
__global__ void meanF_kernel() {
    int b = blockIdx.x >> 1, ch = blockIdx.x & 1;
    int cl = b >> 6, g = b & 63;
    int f = threadIdx.x;
    const float* h = g_hP[cl] + ((size_t)g * KSEL + ch * 128) * 128;
    float acc = 0.f;
#pragma unroll 4
    for (int j = 0; j < 128; j++) acc += h[(size_t)j * 128 + f];
    atomicAdd(&g_meanF[cl][g * 128 + f], acc);
}

__global__ void cF_kernel(const float* __restrict__ Wg) {
    int b = blockIdx.x;
    int cl = b >> 6, g = b & 63;
    int f = threadIdx.x;
    __shared__ float m[128];
    m[f] = g_meanF[cl][g * 128 + f] * (1.f / 256.f);
    __syncthreads();
    float acc = 0.f;
    for (int k = 0; k < 128; k++) acc = fmaf(m[k], Wg[k * 128 + f], acc);
    g_cF[cl][g * 128 + f] = tanhf(acc);
}

// fused alphaP + gfin: one hP pass.
__global__ void __launch_bounds__(256) alphagfin_kernel() {
    int blk = blockIdx.x;
    int cl = blk >> 8;
    int within = blk & 255;
    int g = within >> 2, ch = within & 3;
    int baseRow = g * KSEL + ch * 64;
    int wid = threadIdx.x >> 5, lane = threadIdx.x & 31;
    __shared__ float csh[128];
    __shared__ float accsh[128];
    if (threadIdx.x < 128) {
        csh[threadIdx.x] = g_cF[cl][g * 128 + threadIdx.x];
        accsh[threadIdx.x] = 0.f;
    }
    __syncthreads();
    float acc[4];
#pragma unroll
    for (int q = 0; q < 4; q++) acc[q] = 0.f;
    for (int j = 0; j < 8; j++) {
        int row = baseRow + wid * 8 + j;
        const float* h = g_hP[cl] + (size_t)row * 128;
        float hv[4];
        float dot = 0.f;
#pragma unroll
        for (int q = 0; q < 4; q++) {
            int f = q * 32 + lane;
            hv[q] = h[f];
            dot = fmaf(hv[q], csh[f], dot);
        }
#pragma unroll
        for (int o = 16; o; o >>= 1) dot += __shfl_xor_sync(0xffffffffu, dot, o);
        float alpha = sigmoidf_(dot);
#pragma unroll
        for (int q = 0; q < 4; q++) acc[q] = fmaf(hv[q], alpha, acc[q]);
    }
#pragma unroll
    for (int q = 0; q < 4; q++) atomicAdd(&accsh[q * 32 + lane], acc[q]);
    __syncthreads();
    if (threadIdx.x < 128) atomicAdd(&g_gfin[cl][g * 128 + threadIdx.x], accsh[threadIdx.x]);
}

// ---------------- final MLP ----------------
__global__ void mlp_kernel(const float* __restrict__ Wl1, const float* __restrict__ bl1,
                           const float* __restrict__ Wl2, const float* __restrict__ bl2,
                           const float* __restrict__ Wl3, const float* __restrict__ bl3,
                           float* __restrict__ out)
{
    __shared__ float in[256];
    __shared__ float z1[128];
    __shared__ float z2[64];
    int g = blockIdx.x, t = threadIdx.x;
    in[t] = g_gfin[0][g * 128 + t];
    in[128 + t] = g_gfin[1][g * 128 + t];
    __syncthreads();
    float a = bl1[t];
    for (int k = 0; k < 256; k++) a = fmaf(in[k], Wl1[k * 128 + t], a);
    z1[t] = fmaxf(a, 0.f);
    __syncthreads();
    if (t < 64) {
        float a2 = bl2[t];
        for (int k = 0; k < 128; k++) a2 = fmaf(z1[k], Wl2[k * 64 + t], a2);
        z2[t] = fmaxf(a2, 0.f);
    }
    __syncthreads();
    if (t < 2) {
        float a3 = bl3[t];
        for (int k = 0; k < 64; k++) a3 = fmaf(z2[k], Wl3[k * 2 + t], a3);
        out[g * 2 + t] = a3;
    }
}

// ---------------- host orchestration (single stream, graph-capture safe) ----------------
extern "C" void kernel_launch(void* const* d_in, const int* in_sizes, int n_in,
                              void* d_out, int out_size)
{
    const float* x       = (const float*)d_in[0];
    const int*   src_all = (const int*)d_in[1];
    const int*   dst_all = (const int*)d_in[2];
    const int*   src_c[2] = { (const int*)d_in[3], (const int*)d_in[5] };
    const int*   dst_c[2] = { (const int*)d_in[4], (const int*)d_in[6] };
    const float* W1 = (const float*)d_in[7];  const float* b1 = (const float*)d_in[8];
    const float* W2 = (const float*)d_in[9];  const float* b2 = (const float*)d_in[10];
    const float* W3 = (const float*)d_in[11]; const float* b3 = (const float*)d_in[12];
    const float* Wg_att = (const float*)d_in[13];
    const float* Wal = (const float*)d_in[14]; const float* bal = (const float*)d_in[15];
    const float* Wf  = (const float*)d_in[16]; const float* bf  = (const float*)d_in[17];
    const float* Wg_fin = (const float*)d_in[18];
    const float* Wl1 = (const float*)d_in[19]; const float* bl1 = (const float*)d_in[20];
    const float* Wl2 = (const float*)d_in[21]; const float* bl2 = (const float*)d_in[22];
    const float* Wl3 = (const float*)d_in[23]; const float* bl3 = (const float*)d_in[24];

    void* p;
    cudaGetSymbolAddress(&p, g_h0);        float* h0   = (float*)p;
    cudaGetSymbolAddress(&p, g_h1);        float* h1   = (float*)p;
    cudaGetSymbolAddress(&p, g_h2);        float* h2   = (float*)p;
    cudaGetSymbolAddress(&p, g_xw);        float* xw   = (float*)p;
    cudaGetSymbolAddress(&p, g_dis);       float* dis  = (float*)p;
    cudaGetSymbolAddress(&p, g_degI);      int* degI   = (int*)p;
    cudaGetSymbolAddress(&p, g_rowstart);  int* rowst  = (int*)p;
    cudaGetSymbolAddress(&p, g_cursor);    int* cursor = (int*)p;
    cudaGetSymbolAddress(&p, g_ecol);      int* ecol   = (int*)p;
    cudaGetSymbolAddress(&p, g_ctr);       int* ctr    = (int*)p;
    cudaGetSymbolAddress(&p, g_degPI);     int* degPI  = (int*)p;
    cudaGetSymbolAddress(&p, g_rowstartP); int* rowstP = (int*)p;
    cudaGetSymbolAddress(&p, g_cursorP);   int* cursP  = (int*)p;
    cudaGetSymbolAddress(&p, g_ecolP);     int* ecolP  = (int*)p;
    cudaGetSymbolAddress(&p, g_disP);      float* disP = (float*)p;
    cudaGetSymbolAddress(&p, g_xwP);       float* xwP  = (float*)p;
    cudaGetSymbolAddress(&p, g_hP);        float* hP   = (float*)p;

    static bool attr_done = false;
    if (!attr_done) {
        cudaFuncSetAttribute(gemm_bf16, cudaFuncAttributeMaxDynamicSharedMemorySize, GEMM_SMEM);
        cudaFuncSetAttribute(gemm_pool, cudaFuncAttributeMaxDynamicSharedMemorySize, GEMM_SMEM);
        attr_done = true;
    }

    // launches 1-3, then #4 = the big GEMM (ncu window lands on the 4th launch)
    zero_all_kernel<<<256, 256>>>();                                         // 1
    degi_kernel<<<E_ALL / 256, 256>>>(dst_all, degI, E_ALL);                 // 2
    assign_kernel<<<NTOT / 256, 256>>>(degI, rowst, cursor, dis, NTOT, ctr); // 3
    gemm_bf16<<<NTOT / 128, 256, GEMM_SMEM>>>(x, W1, xw, 128);               // 4  <-- profiled

    place_kernel<<<E_ALL / 256, 256>>>(src_all, dst_all, cursor, ecol, E_ALL);

    // ---- 3 GCN layers ----
    agg_kernel<<<NTOT / 8, 256>>>(xw, rowst, degI, ecol, dis, b1, h0, NTOT);
    gemm_bf16<<<NTOT / 128, 256, GEMM_SMEM>>>(h0, W2, xw, 128);
    agg_kernel<<<NTOT / 8, 256>>>(xw, rowst, degI, ecol, dis, b2, h1, NTOT);
    gemm_bf16<<<NTOT / 128, 256, GEMM_SMEM>>>(h1, W3, xw, 128);
    agg_kernel<<<NTOT / 8, 256>>>(xw, rowst, degI, ecol, dis, b3, h2, NTOT);

    // ---- dual attention pooling ----
    mean384_kernel<<<512, 384>>>();
    catt_kernel<<<128, 384>>>(Wg_att);
    alphagp_kernel<<<1024, 256>>>();
    pv_kernel<<<64, 768>>>(Wal, bal);
    pvnorm_kernel<<<128, 128>>>();

    // ---- CAG pool ----
    score_kernel<<<NTOT / 8, 256>>>();
    topk_kernel<<<128, 512>>>();

    // ---- pooled CSR (combined over both clusters, scan-free) ----
    degPI2_kernel<<<(2 * E_C) / 256, 256>>>(src_c[0], dst_c[0], src_c[1], dst_c[1]);
    assign_kernel<<<(2 * NPOOL) / 256, 256>>>(degPI, rowstP, cursP, disP, 2 * NPOOL, ctr + 1);
    placeP2_kernel<<<(2 * E_C) / 256, 256>>>(src_c[0], dst_c[0], src_c[1], dst_c[1]);

    // ---- pooled GCN: GEMM with fused gather + one agg ----
    gemm_pool<<<(2 * NPOOL) / 128, 256, GEMM_SMEM>>>(Wf, xwP);
    agg_kernel<<<(2 * NPOOL) / 8, 256>>>(xwP, rowstP, degPI, ecolP, disP, bf, hP, 2 * NPOOL);

    // ---- final attention pools + MLP head ----
    meanF_kernel<<<256, 128>>>();
    cF_kernel<<<128, 128>>>(Wg_fin);
    alphagfin_kernel<<<512, 256>>>();
    mlp_kernel<<<64, 128>>>(Wl1, bl1, Wl2, bl2, Wl3, bl3, (float*)d_out);
}